// round 13
// baseline (speedup 1.0000x reference)
#include <cuda_runtime.h>
#include <cuda_bf16.h>

#define B_ 4
#define S_ 512
#define D_ 256
#define U_ 128

// scratch for projections (allocation-free rule: device globals)
__device__ float g_Q[B_ * S_ * U_];
__device__ float g_V[B_ * S_ * U_];

__device__ __forceinline__ float tanh_fast(float x) {
    float y;
    asm("tanh.approx.f32 %0, %1;" : "=f"(y) : "f"(x));
    return y;
}

// 8-u partial score: sum_u w_u * tanh(q_u + v_u)
__device__ __forceinline__ float score8(const float4& qa, const float4& qb,
                                        const float4& va, const float4& vb,
                                        const float4& wa, const float4& wb) {
    float a = tanh_fast(qa.x + va.x) * wa.x;
    a = fmaf(tanh_fast(qa.y + va.y), wa.y, a);
    a = fmaf(tanh_fast(qa.z + va.z), wa.z, a);
    a = fmaf(tanh_fast(qa.w + va.w), wa.w, a);
    a = fmaf(tanh_fast(qb.x + vb.x), wb.x, a);
    a = fmaf(tanh_fast(qb.y + vb.y), wb.y, a);
    a = fmaf(tanh_fast(qb.z + vb.z), wb.z, a);
    a = fmaf(tanh_fast(qb.w + vb.w), wb.w, a);
    return a;
}

// ---------------------------------------------------------------------------
// Kernel 1: Q = values @ Wq, V = values @ Wv   (fused, both share values tile)
// ---------------------------------------------------------------------------
__global__ void proj_kernel(const float* __restrict__ values,
                            const float* __restrict__ Wq,
                            const float* __restrict__ Wv) {
    __shared__ float sv[8][256];   // 8 rows of values
    const int t = threadIdx.x;
    const int rowbase = blockIdx.x * 8;

    {
        const float4* src = (const float4*)(values + rowbase * D_);
        float4* dst = (float4*)&sv[0][0];
        #pragma unroll
        for (int i = 0; i < 2; i++) dst[t + i * 256] = src[t + i * 256];
    }
    __syncthreads();

    const int u = t & 127;
    const float* __restrict__ W = (t < 128) ? Wq : Wv;
    float* __restrict__ G = (t < 128) ? g_Q : g_V;

    float acc[8];
    #pragma unroll
    for (int r = 0; r < 8; r++) acc[r] = 0.f;

    #pragma unroll 4
    for (int k = 0; k < D_; k += 4) {
        const float w0 = W[(k + 0) * U_ + u];
        const float w1 = W[(k + 1) * U_ + u];
        const float w2 = W[(k + 2) * U_ + u];
        const float w3 = W[(k + 3) * U_ + u];
        #pragma unroll
        for (int r = 0; r < 8; r++) {
            float4 v = *(const float4*)&sv[r][k];
            acc[r] = fmaf(v.x, w0, acc[r]);
            acc[r] = fmaf(v.y, w1, acc[r]);
            acc[r] = fmaf(v.z, w2, acc[r]);
            acc[r] = fmaf(v.w, w3, acc[r]);
        }
    }

    #pragma unroll
    for (int r = 0; r < 8; r++)
        G[(rowbase + r) * U_ + u] = acc[r];
}

// ---------------------------------------------------------------------------
// Kernel 2: fused score + softmax + context.
// One CTA per balanced row pair (i0 = p, i1 = S-1-p). grid = B*S/2, 256 thr.
//
// Score phase is BARRIER-FREE and LDS-FREE: each v element is consumed by
// exactly one thread, so v streams directly from L2 (g_V is L2-resident),
// software-pipelined depth-2 to hide ~260cyc L2 latency. q1/q0/Vw chunks are
// register-resident (uc = t&15 owns 8 u-values; jp = t>>4 owns the j lane).
// Cross-u reduction: 16-lane shfl tree; two chains (rows i1,i0) interleave.
//
// smem (static, 12.4 KB -> occupancy reg-limited):
//   red  : 2048 floats (context partial reduction)
//   sc1  : 512 floats (exp scores row i1)
//   sc0  : 512 floats (exp scores row i0)
//   redsc: 16 floats
// ---------------------------------------------------------------------------
__global__ void __launch_bounds__(256)
attn_kernel(const float* __restrict__ values,
            const float* __restrict__ Vw,
            float* __restrict__ out) {
    __shared__ float red[2048];
    __shared__ float sc1[S_];
    __shared__ float sc0[S_];
    __shared__ float redsc[16];

    const int t = threadIdx.x;
    const int b = blockIdx.x >> 8;
    const int p = blockIdx.x & 255;
    const int i0 = p;
    const int i1 = S_ - 1 - p;

    const float* __restrict__ gQb = g_Q + b * S_ * U_;
    const float* __restrict__ gVb = g_V + b * S_ * U_;
    const float* __restrict__ valb = values + b * S_ * D_;

    const int uc = t & 15;        // u-chunk: 8 u-values
    const int jp = t >> 4;        // 0..15: j residue

    // register-resident q1/q0/Vw chunks (loaded once, L2 broadcast)
    const float4 q1a = ((const float4*)(gQb + i1 * U_))[uc * 2 + 0];
    const float4 q1b = ((const float4*)(gQb + i1 * U_))[uc * 2 + 1];
    const float4 q0a = ((const float4*)(gQb + i0 * U_))[uc * 2 + 0];
    const float4 q0b = ((const float4*)(gQb + i0 * U_))[uc * 2 + 1];
    const float4 wa  = ((const float4*)Vw)[uc * 2 + 0];
    const float4 wb  = ((const float4*)Vw)[uc * 2 + 1];

    // ---- score phase: passes of 16 j, depth-2 pipelined global v loads ----
    {
        const int jb = jp & ~1;                       // warp-uniform
        const int P  = (i1 - jb) / 16 + 1;            // total passes (row1)
        const int P0 = (i0 >= jb) ? ((i0 - jb) / 16 + 1) : 0;  // both-row passes

        // v address for pass p, clamped to valid row
        const float4* __restrict__ vbase = (const float4*)gVb + uc * 2;

        float4 va0, vb0, va1, vb1;
        {
            int j0 = jp;               // pass 0 (always valid: jp<=15<=i1? i1>=256 yes)
            const float4* s = vbase + j0 * 32;
            va0 = s[0]; vb0 = s[1];
            int j1 = jp + 16; if (j1 > i1) j1 = i1;
            const float4* s1 = vbase + j1 * 32;
            va1 = s1[0]; vb1 = s1[1];
        }

        for (int ps = 0; ps < P; ps++) {
            // prefetch pass ps+2
            float4 nva = va1, nvb = vb1;
            if (ps + 2 < P) {
                int jn = jp + (ps + 2) * 16;
                if (jn > i1) jn = i1;
                const float4* s = vbase + jn * 32;
                nva = s[0]; nvb = s[1];
            }

            const int j = jp + ps * 16;
            const bool do0 = (ps < P0);               // warp-uniform

            float a1 = score8(q1a, q1b, va0, vb0, wa, wb);
            if (do0) {
                float a0 = score8(q0a, q0b, va0, vb0, wa, wb);
                #pragma unroll
                for (int o = 8; o; o >>= 1) {
                    a1 += __shfl_xor_sync(0xffffffffu, a1, o);
                    a0 += __shfl_xor_sync(0xffffffffu, a0, o);
                }
                if (uc == 0) {
                    sc1[j] = a1;                      // j<=i0<=i1 here
                    if (j <= i0) sc0[j] = a0;
                }
            } else {
                #pragma unroll
                for (int o = 8; o; o >>= 1)
                    a1 += __shfl_xor_sync(0xffffffffu, a1, o);
                if (uc == 0 && j <= i1) sc1[j] = a1;
            }

            va0 = va1; vb0 = vb1;
            va1 = nva; vb1 = nvb;
        }
    }
    __syncthreads();

    // ---- softmax stats (exp in-place; 1/sum folded into context) ----
    {
        const bool row1 = (t < 128);
        const int  hl   = t & 127;
        float* sc = row1 ? sc1 : sc0;
        const int L = (row1 ? i1 : i0) + 1;
        const int wid = t >> 5;
        const int base = row1 ? 0 : 4;

        float m = -3.4e38f;
        for (int j = hl; j < L; j += 128) m = fmaxf(m, sc[j]);
        #pragma unroll
        for (int o = 16; o; o >>= 1) m = fmaxf(m, __shfl_xor_sync(0xffffffffu, m, o));
        if ((t & 31) == 0) redsc[wid] = m;
        __syncthreads();
        m = fmaxf(fmaxf(redsc[base], redsc[base + 1]),
                  fmaxf(redsc[base + 2], redsc[base + 3]));

        float s = 0.f;
        for (int j = hl; j < L; j += 128) {
            float e = __expf(sc[j] - m);
            sc[j] = e;
            s += e;
        }
        #pragma unroll
        for (int o = 16; o; o >>= 1) s += __shfl_xor_sync(0xffffffffu, s, o);
        __syncthreads();              // protect redsc reuse
        if ((t & 31) == 0) redsc[wid] = s;
        __syncthreads();
        s = redsc[base] + redsc[base + 1] + redsc[base + 2] + redsc[base + 3];
        if (hl == 0) redsc[8 + (row1 ? 0 : 1)] = 1.0f / s;   // inv1 @8, inv0 @9
        __syncthreads();
    }

    // ---- context: out[i] = inv * sum_j exp_j * values[b,j,:] ----
    {
        const int jg = t >> 6;            // 0..3 : j residue class
        const int dg = (t & 63) << 2;     // float4 column base
        float4 A1 = make_float4(0.f, 0.f, 0.f, 0.f);
        float4 A0 = make_float4(0.f, 0.f, 0.f, 0.f);

        #pragma unroll 2
        for (int j = jg; j <= i1; j += 4) {
            float4 v = *(const float4*)&valb[j * D_ + dg];
            float p1 = sc1[j];
            A1.x = fmaf(p1, v.x, A1.x);
            A1.y = fmaf(p1, v.y, A1.y);
            A1.z = fmaf(p1, v.z, A1.z);
            A1.w = fmaf(p1, v.w, A1.w);
            if (j <= i0) {
                float p0 = sc0[j];
                A0.x = fmaf(p0, v.x, A0.x);
                A0.y = fmaf(p0, v.y, A0.y);
                A0.z = fmaf(p0, v.z, A0.z);
                A0.w = fmaf(p0, v.w, A0.w);
            }
        }

        // partial reduction across the 4 j-classes via smem
        float4* red4 = (float4*)red;
        red4[(jg * 2 + 0) * 64 + (t & 63)] = A1;
        red4[(jg * 2 + 1) * 64 + (t & 63)] = A0;
        __syncthreads();

        const bool row1 = (t < 128);
        const int  hl   = t & 127;
        const int  i    = row1 ? i1 : i0;
        const int  slot = row1 ? 0 : 1;
        const float inv = redsc[8 + slot];
        float* ob = out + (b * S_ + i) * D_;
        #pragma unroll
        for (int h = 0; h < 2; h++) {
            int d = hl + h * 128;
            float o = red[(0 * 2 + slot) * 256 + d]
                    + red[(1 * 2 + slot) * 256 + d]
                    + red[(2 * 2 + slot) * 256 + d]
                    + red[(3 * 2 + slot) * 256 + d];
            ob[d] = o * inv;
        }
    }
}

// ---------------------------------------------------------------------------
extern "C" void kernel_launch(void* const* d_in, const int* in_sizes, int n_in,
                              void* d_out, int out_size) {
    const float* values = (const float*)d_in[0];
    const float* Wq     = (const float*)d_in[1];
    const float* Wv     = (const float*)d_in[2];
    const float* Vw     = (const float*)d_in[3];
    float* out = (float*)d_out;

    proj_kernel<<<(B_ * S_) / 8, 256>>>(values, Wq, Wv);
    attn_kernel<<<B_ * (S_ / 2), 256>>>(values, Vw, out);
}

// round 14
// speedup vs baseline: 1.5278x; 1.5278x over previous
#include <cuda_runtime.h>
#include <cuda_bf16.h>

#define B_ 4
#define S_ 512
#define D_ 256
#define U_ 128

// scratch for projections (allocation-free rule: device globals)
__device__ float g_Q[B_ * S_ * U_];
__device__ float g_V[B_ * S_ * U_];

__device__ __forceinline__ float tanh_fast(float x) {
    float y;
    asm("tanh.approx.f32 %0, %1;" : "=f"(y) : "f"(x));
    return y;
}

// 8-u partial score: sum_u w_u * tanh(q_u + v_u)
__device__ __forceinline__ float score8(const float4& qa, const float4& qb,
                                        const float4& va, const float4& vb,
                                        const float4& wa, const float4& wb) {
    float a = tanh_fast(qa.x + va.x) * wa.x;
    a = fmaf(tanh_fast(qa.y + va.y), wa.y, a);
    a = fmaf(tanh_fast(qa.z + va.z), wa.z, a);
    a = fmaf(tanh_fast(qa.w + va.w), wa.w, a);
    a = fmaf(tanh_fast(qb.x + vb.x), wb.x, a);
    a = fmaf(tanh_fast(qb.y + vb.y), wb.y, a);
    a = fmaf(tanh_fast(qb.z + vb.z), wb.z, a);
    a = fmaf(tanh_fast(qb.w + vb.w), wb.w, a);
    return a;
}

// ---------------------------------------------------------------------------
// Kernel 1: Q = values @ Wq, V = values @ Wv   (fused, both share values tile)
// ---------------------------------------------------------------------------
__global__ void proj_kernel(const float* __restrict__ values,
                            const float* __restrict__ Wq,
                            const float* __restrict__ Wv) {
    __shared__ float sv[8][256];   // 8 rows of values
    const int t = threadIdx.x;
    const int rowbase = blockIdx.x * 8;

    {
        const float4* src = (const float4*)(values + rowbase * D_);
        float4* dst = (float4*)&sv[0][0];
        #pragma unroll
        for (int i = 0; i < 2; i++) dst[t + i * 256] = src[t + i * 256];
    }
    __syncthreads();

    const int u = t & 127;
    const float* __restrict__ W = (t < 128) ? Wq : Wv;
    float* __restrict__ G = (t < 128) ? g_Q : g_V;

    float acc[8];
    #pragma unroll
    for (int r = 0; r < 8; r++) acc[r] = 0.f;

    #pragma unroll 4
    for (int k = 0; k < D_; k += 4) {
        const float w0 = W[(k + 0) * U_ + u];
        const float w1 = W[(k + 1) * U_ + u];
        const float w2 = W[(k + 2) * U_ + u];
        const float w3 = W[(k + 3) * U_ + u];
        #pragma unroll
        for (int r = 0; r < 8; r++) {
            float4 v = *(const float4*)&sv[r][k];
            acc[r] = fmaf(v.x, w0, acc[r]);
            acc[r] = fmaf(v.y, w1, acc[r]);
            acc[r] = fmaf(v.z, w2, acc[r]);
            acc[r] = fmaf(v.w, w3, acc[r]);
        }
    }

    #pragma unroll
    for (int r = 0; r < 8; r++)
        G[(rowbase + r) * U_ + u] = acc[r];
}

// ---------------------------------------------------------------------------
// Kernel 2: fused score + softmax + context, FOUR rows per CTA.
// Rows: A=i1a=511-2c, B=i1b=510-2c, C=i0a=2c, D=i0b=2c+1 (two balanced
// pairs -> every CTA does 2*(S+1) score columns). grid = B*128 = 512 CTAs
// -> SINGLE WAVE at 4 CTAs/SM.
//
// Score phase: q for all 4 rows + Vw in registers (uc = t&15 owns 8 u);
// jp = t>>4 owns the j lane. v tile in smem (pad-132), each v element read
// once and shared by 4 rows. 4 interleaved shfl trees per pass.
//
// smem: vt 33792 B (context red 16KB aliases it) + sc 4x512x4 = 8192 B
//       + redsc 64 B  => 42048 B -> 4 CTAs/SM.
// ---------------------------------------------------------------------------
#define SMEM_BYTES 42048

__global__ void __launch_bounds__(256)
attn_kernel(const float* __restrict__ values,
            const float* __restrict__ Vw,
            float* __restrict__ out) {
    extern __shared__ char smem[];
    float* vt    = (float*)smem;               // 64 x 132 floats
    float* red   = (float*)smem;               // aliases vt (context phase)
    float* scA   = (float*)(smem + 33792);     // row i1a
    float* scB   = scA + 512;                  // row i1b
    float* scC   = scB + 512;                  // row i0a
    float* scD   = scC + 512;                  // row i0b
    float* redsc = scD + 512;                  // 16 floats

    const int t = threadIdx.x;
    const int b = blockIdx.x >> 7;
    const int c = blockIdx.x & 127;
    const int i0a = 2 * c;
    const int i0b = 2 * c + 1;
    const int i1b = 510 - 2 * c;
    const int i1a = 511 - 2 * c;

    const float* __restrict__ gQb = g_Q + b * S_ * U_;
    const float* __restrict__ gVb = g_V + b * S_ * U_;
    const float* __restrict__ valb = values + b * S_ * D_;

    const int uc = t & 15;        // u-chunk: 8 u-values
    const int jp = t >> 4;        // 0..15: j within pass

    // register-resident q (4 rows) + Vw chunks
    const float4 qAa = ((const float4*)(gQb + i1a * U_))[uc * 2 + 0];
    const float4 qAb = ((const float4*)(gQb + i1a * U_))[uc * 2 + 1];
    const float4 qBa = ((const float4*)(gQb + i1b * U_))[uc * 2 + 0];
    const float4 qBb = ((const float4*)(gQb + i1b * U_))[uc * 2 + 1];
    const float4 qCa = ((const float4*)(gQb + i0a * U_))[uc * 2 + 0];
    const float4 qCb = ((const float4*)(gQb + i0a * U_))[uc * 2 + 1];
    const float4 qDa = ((const float4*)(gQb + i0b * U_))[uc * 2 + 0];
    const float4 qDb = ((const float4*)(gQb + i0b * U_))[uc * 2 + 1];
    const float4 wa  = ((const float4*)Vw)[uc * 2 + 0];
    const float4 wb  = ((const float4*)Vw)[uc * 2 + 1];

    // ---- score phase: tiles of 64 j-columns ----
    for (int jt = 0; jt <= i1a; jt += 64) {
        // load v tile [64 x 128] -> vt (pad 132)
        {
            const float4* src = (const float4*)(gVb + jt * U_);
            float4* dst = (float4*)vt;
            #pragma unroll
            for (int it = 0; it < 8; it++) {
                int idx4 = t + it * 256;          // 0..2047
                float4 v = src[idx4];
                int jr = idx4 >> 5;
                int u4 = idx4 & 31;
                dst[jr * 33 + u4] = v;
            }
        }
        __syncthreads();

        if (jt + 63 <= i0a) {
            // ---- FAST PATH: full for ALL FOUR rows ----
            #pragma unroll
            for (int ps = 0; ps < 4; ps++) {
                const int j = jt + ps * 16 + jp;
                const float4* __restrict__ v4 =
                    (const float4*)(vt + (ps * 16 + jp) * 132) + uc * 2;
                const float4 va = v4[0], vb = v4[1];

                float aA = score8(qAa, qAb, va, vb, wa, wb);
                float aB = score8(qBa, qBb, va, vb, wa, wb);
                float aC = score8(qCa, qCb, va, vb, wa, wb);
                float aD = score8(qDa, qDb, va, vb, wa, wb);
                #pragma unroll
                for (int o = 8; o; o >>= 1) {
                    aA += __shfl_xor_sync(0xffffffffu, aA, o);
                    aB += __shfl_xor_sync(0xffffffffu, aB, o);
                    aC += __shfl_xor_sync(0xffffffffu, aC, o);
                    aD += __shfl_xor_sync(0xffffffffu, aD, o);
                }
                if (uc == 0) {
                    scA[j] = aA; scB[j] = aB; scC[j] = aC; scD[j] = aD;
                }
            }
        } else if (jt > i0b && jt + 63 <= i1b) {
            // ---- FAST PATH: full for rows A,B only ----
            #pragma unroll
            for (int ps = 0; ps < 4; ps += 2) {
                const int jA = jt + ps * 16 + jp;
                const int jB = jt + (ps + 1) * 16 + jp;
                const float4* __restrict__ vA =
                    (const float4*)(vt + (ps * 16 + jp) * 132) + uc * 2;
                const float4* __restrict__ vB =
                    (const float4*)(vt + ((ps + 1) * 16 + jp) * 132) + uc * 2;
                const float4 vA0 = vA[0], vA1 = vA[1];
                const float4 vB0 = vB[0], vB1 = vB[1];

                float aA0 = score8(qAa, qAb, vA0, vA1, wa, wb);
                float aB0 = score8(qBa, qBb, vA0, vA1, wa, wb);
                float aA1 = score8(qAa, qAb, vB0, vB1, wa, wb);
                float aB1 = score8(qBa, qBb, vB0, vB1, wa, wb);
                #pragma unroll
                for (int o = 8; o; o >>= 1) {
                    aA0 += __shfl_xor_sync(0xffffffffu, aA0, o);
                    aB0 += __shfl_xor_sync(0xffffffffu, aB0, o);
                    aA1 += __shfl_xor_sync(0xffffffffu, aA1, o);
                    aB1 += __shfl_xor_sync(0xffffffffu, aB1, o);
                }
                if (uc == 0) {
                    scA[jA] = aA0; scB[jA] = aB0;
                    scA[jB] = aA1; scB[jB] = aB1;
                }
            }
        } else {
            // ---- BOUNDARY tile: per-pass warp-uniform guards ----
            #pragma unroll
            for (int ps = 0; ps < 4; ps++) {
                const int j = jt + ps * 16 + jp;
                const int jwmin = j - (jp & 1);       // warp-uniform min j
                if (jwmin > i1a) break;               // warp-uniform

                const float4* __restrict__ v4 =
                    (const float4*)(vt + (ps * 16 + jp) * 132) + uc * 2;
                const float4 va = v4[0], vb = v4[1];

                // rows A,B (i1a, i1b=i1a-1)
                float aA = score8(qAa, qAb, va, vb, wa, wb);
                float aB = score8(qBa, qBb, va, vb, wa, wb);
                #pragma unroll
                for (int o = 8; o; o >>= 1) {
                    aA += __shfl_xor_sync(0xffffffffu, aA, o);
                    aB += __shfl_xor_sync(0xffffffffu, aB, o);
                }
                if (uc == 0) {
                    if (j <= i1a) scA[j] = aA;
                    if (j <= i1b) scB[j] = aB;
                }

                // rows C,D (i0a, i0b=i0a+1)
                if (jwmin <= i0b) {
                    float aC = score8(qCa, qCb, va, vb, wa, wb);
                    float aD = score8(qDa, qDb, va, vb, wa, wb);
                    #pragma unroll
                    for (int o = 8; o; o >>= 1) {
                        aC += __shfl_xor_sync(0xffffffffu, aC, o);
                        aD += __shfl_xor_sync(0xffffffffu, aD, o);
                    }
                    if (uc == 0) {
                        if (j <= i0a) scC[j] = aC;
                        if (j <= i0b) scD[j] = aD;
                    }
                }
            }
        }
        __syncthreads();
    }

    // ---- softmax stats: 64 threads per row (r = t>>6) ----
    {
        const int r  = t >> 6;
        const int hl = t & 63;
        float* sc = scA + r * 512;
        const int ri = (r == 0) ? i1a : (r == 1) ? i1b : (r == 2) ? i0a : i0b;
        const int L = ri + 1;
        const int wid = t >> 5;              // 0..7; row r owns warps 2r,2r+1

        float m = -3.4e38f;
        for (int j = hl; j < L; j += 64) m = fmaxf(m, sc[j]);
        #pragma unroll
        for (int o = 16; o; o >>= 1) m = fmaxf(m, __shfl_xor_sync(0xffffffffu, m, o));
        if ((t & 31) == 0) redsc[wid] = m;
        __syncthreads();
        m = fmaxf(redsc[2 * r], redsc[2 * r + 1]);

        float s = 0.f;
        for (int j = hl; j < L; j += 64) {
            float e = __expf(sc[j] - m);
            sc[j] = e;
            s += e;
        }
        #pragma unroll
        for (int o = 16; o; o >>= 1) s += __shfl_xor_sync(0xffffffffu, s, o);
        __syncthreads();              // protect redsc reuse
        if ((t & 31) == 0) redsc[wid] = s;
        __syncthreads();
        s = redsc[2 * r] + redsc[2 * r + 1];
        if (hl == 0) redsc[8 + r] = 1.0f / s;
        __syncthreads();
    }

    // ---- context: out[row] = inv * sum_j exp_j * values[b,j,:] ----
    {
        const int jg = t >> 6;            // 0..3 : j residue class
        const int dl = t & 63;
        const int dg = dl << 2;           // float4 column base
        float4 AA = make_float4(0.f, 0.f, 0.f, 0.f);
        float4 AB = make_float4(0.f, 0.f, 0.f, 0.f);
        float4 AC = make_float4(0.f, 0.f, 0.f, 0.f);
        float4 AD = make_float4(0.f, 0.f, 0.f, 0.f);

        #pragma unroll 2
        for (int j = jg; j <= i1a; j += 4) {
            float4 v = *(const float4*)&valb[j * D_ + dg];
            float pA = scA[j];
            AA.x = fmaf(pA, v.x, AA.x);
            AA.y = fmaf(pA, v.y, AA.y);
            AA.z = fmaf(pA, v.z, AA.z);
            AA.w = fmaf(pA, v.w, AA.w);
            if (j <= i1b) {
                float pB = scB[j];
                AB.x = fmaf(pB, v.x, AB.x);
                AB.y = fmaf(pB, v.y, AB.y);
                AB.z = fmaf(pB, v.z, AB.z);
                AB.w = fmaf(pB, v.w, AB.w);
            }
            if (j <= i0b) {
                float pD = scD[j];
                AD.x = fmaf(pD, v.x, AD.x);
                AD.y = fmaf(pD, v.y, AD.y);
                AD.z = fmaf(pD, v.z, AD.z);
                AD.w = fmaf(pD, v.w, AD.w);
                if (j <= i0a) {
                    float pC = scC[j];
                    AC.x = fmaf(pC, v.x, AC.x);
                    AC.y = fmaf(pC, v.y, AC.y);
                    AC.z = fmaf(pC, v.z, AC.z);
                    AC.w = fmaf(pC, v.w, AC.w);
                }
            }
        }

        // partial reduction across the 4 j-classes via smem (aliases vt)
        float4* red4 = (float4*)red;
        red4[(jg * 4 + 0) * 64 + dl] = AA;
        red4[(jg * 4 + 1) * 64 + dl] = AB;
        red4[(jg * 4 + 2) * 64 + dl] = AC;
        red4[(jg * 4 + 3) * 64 + dl] = AD;
        __syncthreads();

        const int r = t >> 6;
        const int ri = (r == 0) ? i1a : (r == 1) ? i1b : (r == 2) ? i0a : i0b;
        const float inv = redsc[8 + r];
        float* ob = out + (b * S_ + ri) * D_;
        const int hl = t & 63;
        #pragma unroll
        for (int h = 0; h < 4; h++) {
            int d = hl + h * 64;
            float o = red[(0 * 4 + r) * 256 + d]
                    + red[(1 * 4 + r) * 256 + d]
                    + red[(2 * 4 + r) * 256 + d]
                    + red[(3 * 4 + r) * 256 + d];
            ob[d] = o * inv;
        }
    }
}

// ---------------------------------------------------------------------------
extern "C" void kernel_launch(void* const* d_in, const int* in_sizes, int n_in,
                              void* d_out, int out_size) {
    const float* values = (const float*)d_in[0];
    const float* Wq     = (const float*)d_in[1];
    const float* Wv     = (const float*)d_in[2];
    const float* Vw     = (const float*)d_in[3];
    float* out = (float*)d_out;

    cudaFuncSetAttribute(attn_kernel,
                         cudaFuncAttributeMaxDynamicSharedMemorySize, SMEM_BYTES);

    proj_kernel<<<(B_ * S_) / 8, 256>>>(values, Wq, Wv);
    attn_kernel<<<B_ * 128, 256, SMEM_BYTES>>>(values, Vw, out);
}

// round 17
// speedup vs baseline: 1.7166x; 1.1235x over previous
#include <cuda_runtime.h>
#include <cuda_bf16.h>

#define B_ 4
#define S_ 512
#define D_ 256
#define U_ 128

// scratch for projections (allocation-free rule: device globals)
__device__ float g_Q[B_ * S_ * U_];
__device__ float g_V[B_ * S_ * U_];

__device__ __forceinline__ float tanh_fast(float x) {
    float y;
    asm("tanh.approx.f32 %0, %1;" : "=f"(y) : "f"(x));
    return y;
}

// 8-u partial score: sum_u w_u * tanh(q_u + v_u)
__device__ __forceinline__ float score8(const float4& qa, const float4& qb,
                                        const float4& va, const float4& vb,
                                        const float4& wa, const float4& wb) {
    float a = tanh_fast(qa.x + va.x) * wa.x;
    a = fmaf(tanh_fast(qa.y + va.y), wa.y, a);
    a = fmaf(tanh_fast(qa.z + va.z), wa.z, a);
    a = fmaf(tanh_fast(qa.w + va.w), wa.w, a);
    a = fmaf(tanh_fast(qb.x + vb.x), wb.x, a);
    a = fmaf(tanh_fast(qb.y + vb.y), wb.y, a);
    a = fmaf(tanh_fast(qb.z + vb.z), wb.z, a);
    a = fmaf(tanh_fast(qb.w + vb.w), wb.w, a);
    return a;
}

// ---------------------------------------------------------------------------
// Kernel 1: Q = values @ Wq, V = values @ Wv   (fused, both share values tile)
// ---------------------------------------------------------------------------
__global__ void proj_kernel(const float* __restrict__ values,
                            const float* __restrict__ Wq,
                            const float* __restrict__ Wv) {
    __shared__ float sv[8][256];   // 8 rows of values
    const int t = threadIdx.x;
    const int rowbase = blockIdx.x * 8;

    {
        const float4* src = (const float4*)(values + rowbase * D_);
        float4* dst = (float4*)&sv[0][0];
        #pragma unroll
        for (int i = 0; i < 2; i++) dst[t + i * 256] = src[t + i * 256];
    }
    __syncthreads();

    const int u = t & 127;
    const float* __restrict__ W = (t < 128) ? Wq : Wv;
    float* __restrict__ G = (t < 128) ? g_Q : g_V;

    float acc[8];
    #pragma unroll
    for (int r = 0; r < 8; r++) acc[r] = 0.f;

    #pragma unroll 4
    for (int k = 0; k < D_; k += 4) {
        const float w0 = W[(k + 0) * U_ + u];
        const float w1 = W[(k + 1) * U_ + u];
        const float w2 = W[(k + 2) * U_ + u];
        const float w3 = W[(k + 3) * U_ + u];
        #pragma unroll
        for (int r = 0; r < 8; r++) {
            float4 v = *(const float4*)&sv[r][k];
            acc[r] = fmaf(v.x, w0, acc[r]);
            acc[r] = fmaf(v.y, w1, acc[r]);
            acc[r] = fmaf(v.z, w2, acc[r]);
            acc[r] = fmaf(v.w, w3, acc[r]);
        }
    }

    #pragma unroll
    for (int r = 0; r < 8; r++)
        G[(rowbase + r) * U_ + u] = acc[r];
}

// ---------------------------------------------------------------------------
// Kernel 2: fused score + softmax + context, FOUR rows per CTA.
// Rows: A=i1a=511-2c, B=i1b=510-2c, C=i0a=2c, D=i0b=2c+1 (two balanced
// pairs). grid = B*128 = 512 CTAs. Target 4 CTAs/SM -> SINGLE WAVE.
//
// Register budget trick: q rows A,B (used every pass) live in registers;
// q rows C,D (used ~half the passes) live in smem and are re-read per pass.
// __launch_bounds__(256,4) pins regs <= 64.
//
// smem: vt 33792 B (context red aliases it) + sc 4x2048 + redsc 64
//       + qc/qd rows 1024 B => 43072 B -> 4 CTAs/SM (172 KB).
// ---------------------------------------------------------------------------
#define SMEM_BYTES 43072

__global__ void __launch_bounds__(256, 4)
attn_kernel(const float* __restrict__ values,
            const float* __restrict__ Vw,
            float* __restrict__ out) {
    extern __shared__ char smem[];
    float* vt    = (float*)smem;               // 64 x 132 floats
    float* red   = (float*)smem;               // aliases vt (context phase)
    float* scA   = (float*)(smem + 33792);     // row i1a
    float* scB   = scA + 512;                  // row i1b
    float* scC   = scB + 512;                  // row i0a
    float* scD   = scC + 512;                  // row i0b
    float* redsc = scD + 512;                  // 16 floats
    float* qc_s  = redsc + 16;                 // 128 floats (q row i0a)
    float* qd_s  = qc_s + 128;                 // 128 floats (q row i0b)

    const int t = threadIdx.x;
    const int b = blockIdx.x >> 7;
    const int c = blockIdx.x & 127;
    const int i0a = 2 * c;
    const int i0b = 2 * c + 1;
    const int i1b = 510 - 2 * c;
    const int i1a = 511 - 2 * c;

    const float* __restrict__ gQb = g_Q + b * S_ * U_;
    const float* __restrict__ gVb = g_V + b * S_ * U_;
    const float* __restrict__ valb = values + b * S_ * D_;

    const int uc = t & 15;        // u-chunk: 8 u-values
    const int jp = t >> 4;        // 0..15: j within pass

    // q rows C,D -> smem (saves 16 registers)
    if (t < 128)      qc_s[t]      = gQb[i0a * U_ + t];
    else              qd_s[t - 128] = gQb[i0b * U_ + (t - 128)];
    const float4* __restrict__ qc4 = (const float4*)qc_s;
    const float4* __restrict__ qd4 = (const float4*)qd_s;

    // register-resident q rows A,B + Vw chunks
    const float4 qAa = ((const float4*)(gQb + i1a * U_))[uc * 2 + 0];
    const float4 qAb = ((const float4*)(gQb + i1a * U_))[uc * 2 + 1];
    const float4 qBa = ((const float4*)(gQb + i1b * U_))[uc * 2 + 0];
    const float4 qBb = ((const float4*)(gQb + i1b * U_))[uc * 2 + 1];
    const float4 wa  = ((const float4*)Vw)[uc * 2 + 0];
    const float4 wb  = ((const float4*)Vw)[uc * 2 + 1];

    // ---- score phase: tiles of 64 j-columns ----
    for (int jt = 0; jt <= i1a; jt += 64) {
        // load v tile [64 x 128] -> vt (pad 132)
        {
            const float4* src = (const float4*)(gVb + jt * U_);
            float4* dst = (float4*)vt;
            #pragma unroll
            for (int it = 0; it < 8; it++) {
                int idx4 = t + it * 256;          // 0..2047
                float4 v = src[idx4];
                int jr = idx4 >> 5;
                int u4 = idx4 & 31;
                dst[jr * 33 + u4] = v;
            }
        }
        __syncthreads();

        if (jt + 63 <= i0a) {
            // ---- FAST PATH: full for ALL FOUR rows ----
            #pragma unroll
            for (int ps = 0; ps < 4; ps++) {
                const int j = jt + ps * 16 + jp;
                const float4* __restrict__ v4 =
                    (const float4*)(vt + (ps * 16 + jp) * 132) + uc * 2;
                const float4 va = v4[0], vb = v4[1];
                const float4 qCa = qc4[uc * 2 + 0], qCb = qc4[uc * 2 + 1];
                const float4 qDa = qd4[uc * 2 + 0], qDb = qd4[uc * 2 + 1];

                float aA = score8(qAa, qAb, va, vb, wa, wb);
                float aB = score8(qBa, qBb, va, vb, wa, wb);
                float aC = score8(qCa, qCb, va, vb, wa, wb);
                float aD = score8(qDa, qDb, va, vb, wa, wb);
                #pragma unroll
                for (int o = 8; o; o >>= 1) {
                    aA += __shfl_xor_sync(0xffffffffu, aA, o);
                    aB += __shfl_xor_sync(0xffffffffu, aB, o);
                    aC += __shfl_xor_sync(0xffffffffu, aC, o);
                    aD += __shfl_xor_sync(0xffffffffu, aD, o);
                }
                if (uc == 0) {
                    scA[j] = aA; scB[j] = aB; scC[j] = aC; scD[j] = aD;
                }
            }
        } else if (jt > i0b && jt + 63 <= i1b) {
            // ---- FAST PATH: full for rows A,B only ----
            #pragma unroll
            for (int ps = 0; ps < 4; ps += 2) {
                const int jA = jt + ps * 16 + jp;
                const int jB = jt + (ps + 1) * 16 + jp;
                const float4* __restrict__ vA =
                    (const float4*)(vt + (ps * 16 + jp) * 132) + uc * 2;
                const float4* __restrict__ vB =
                    (const float4*)(vt + ((ps + 1) * 16 + jp) * 132) + uc * 2;
                const float4 vA0 = vA[0], vA1 = vA[1];
                const float4 vB0 = vB[0], vB1 = vB[1];

                float aA0 = score8(qAa, qAb, vA0, vA1, wa, wb);
                float aB0 = score8(qBa, qBb, vA0, vA1, wa, wb);
                float aA1 = score8(qAa, qAb, vB0, vB1, wa, wb);
                float aB1 = score8(qBa, qBb, vB0, vB1, wa, wb);
                #pragma unroll
                for (int o = 8; o; o >>= 1) {
                    aA0 += __shfl_xor_sync(0xffffffffu, aA0, o);
                    aB0 += __shfl_xor_sync(0xffffffffu, aB0, o);
                    aA1 += __shfl_xor_sync(0xffffffffu, aA1, o);
                    aB1 += __shfl_xor_sync(0xffffffffu, aB1, o);
                }
                if (uc == 0) {
                    scA[jA] = aA0; scB[jA] = aB0;
                    scA[jB] = aA1; scB[jB] = aB1;
                }
            }
        } else {
            // ---- BOUNDARY tile: per-pass warp-uniform guards ----
            #pragma unroll
            for (int ps = 0; ps < 4; ps++) {
                const int j = jt + ps * 16 + jp;
                const int jwmin = j - (jp & 1);       // warp-uniform min j
                if (jwmin > i1a) break;               // warp-uniform

                const float4* __restrict__ v4 =
                    (const float4*)(vt + (ps * 16 + jp) * 132) + uc * 2;
                const float4 va = v4[0], vb = v4[1];

                // rows A,B (i1a, i1b=i1a-1)
                float aA = score8(qAa, qAb, va, vb, wa, wb);
                float aB = score8(qBa, qBb, va, vb, wa, wb);
                #pragma unroll
                for (int o = 8; o; o >>= 1) {
                    aA += __shfl_xor_sync(0xffffffffu, aA, o);
                    aB += __shfl_xor_sync(0xffffffffu, aB, o);
                }
                if (uc == 0) {
                    if (j <= i1a) scA[j] = aA;
                    if (j <= i1b) scB[j] = aB;
                }

                // rows C,D (i0a, i0b=i0a+1)
                if (jwmin <= i0b) {
                    const float4 qCa = qc4[uc * 2 + 0], qCb = qc4[uc * 2 + 1];
                    const float4 qDa = qd4[uc * 2 + 0], qDb = qd4[uc * 2 + 1];
                    float aC = score8(qCa, qCb, va, vb, wa, wb);
                    float aD = score8(qDa, qDb, va, vb, wa, wb);
                    #pragma unroll
                    for (int o = 8; o; o >>= 1) {
                        aC += __shfl_xor_sync(0xffffffffu, aC, o);
                        aD += __shfl_xor_sync(0xffffffffu, aD, o);
                    }
                    if (uc == 0) {
                        if (j <= i0a) scC[j] = aC;
                        if (j <= i0b) scD[j] = aD;
                    }
                }
            }
        }
        __syncthreads();
    }

    // ---- softmax stats: 64 threads per row (r = t>>6) ----
    {
        const int r  = t >> 6;
        const int hl = t & 63;
        float* sc = scA + r * 512;
        const int ri = (r == 0) ? i1a : (r == 1) ? i1b : (r == 2) ? i0a : i0b;
        const int L = ri + 1;
        const int wid = t >> 5;              // 0..7; row r owns warps 2r,2r+1

        float m = -3.4e38f;
        for (int j = hl; j < L; j += 64) m = fmaxf(m, sc[j]);
        #pragma unroll
        for (int o = 16; o; o >>= 1) m = fmaxf(m, __shfl_xor_sync(0xffffffffu, m, o));
        if ((t & 31) == 0) redsc[wid] = m;
        __syncthreads();
        m = fmaxf(redsc[2 * r], redsc[2 * r + 1]);

        float s = 0.f;
        for (int j = hl; j < L; j += 64) {
            float e = __expf(sc[j] - m);
            sc[j] = e;
            s += e;
        }
        #pragma unroll
        for (int o = 16; o; o >>= 1) s += __shfl_xor_sync(0xffffffffu, s, o);
        __syncthreads();              // protect redsc reuse
        if ((t & 31) == 0) redsc[wid] = s;
        __syncthreads();
        s = redsc[2 * r] + redsc[2 * r + 1];
        if (hl == 0) redsc[8 + r] = 1.0f / s;
        __syncthreads();
    }

    // ---- context: out[row] = inv * sum_j exp_j * values[b,j,:] ----
    {
        const int jg = t >> 6;            // 0..3 : j residue class
        const int dl = t & 63;
        const int dg = dl << 2;           // float4 column base
        float4 AA = make_float4(0.f, 0.f, 0.f, 0.f);
        float4 AB = make_float4(0.f, 0.f, 0.f, 0.f);
        float4 AC = make_float4(0.f, 0.f, 0.f, 0.f);
        float4 AD = make_float4(0.f, 0.f, 0.f, 0.f);

        #pragma unroll 2
        for (int j = jg; j <= i1a; j += 4) {
            float4 v = *(const float4*)&valb[j * D_ + dg];
            float pA = scA[j];
            AA.x = fmaf(pA, v.x, AA.x);
            AA.y = fmaf(pA, v.y, AA.y);
            AA.z = fmaf(pA, v.z, AA.z);
            AA.w = fmaf(pA, v.w, AA.w);
            if (j <= i1b) {
                float pB = scB[j];
                AB.x = fmaf(pB, v.x, AB.x);
                AB.y = fmaf(pB, v.y, AB.y);
                AB.z = fmaf(pB, v.z, AB.z);
                AB.w = fmaf(pB, v.w, AB.w);
            }
            if (j <= i0b) {
                float pD = scD[j];
                AD.x = fmaf(pD, v.x, AD.x);
                AD.y = fmaf(pD, v.y, AD.y);
                AD.z = fmaf(pD, v.z, AD.z);
                AD.w = fmaf(pD, v.w, AD.w);
                if (j <= i0a) {
                    float pC = scC[j];
                    AC.x = fmaf(pC, v.x, AC.x);
                    AC.y = fmaf(pC, v.y, AC.y);
                    AC.z = fmaf(pC, v.z, AC.z);
                    AC.w = fmaf(pC, v.w, AC.w);
                }
            }
        }

        // partial reduction across the 4 j-classes via smem (aliases vt)
        float4* red4 = (float4*)red;
        red4[(jg * 4 + 0) * 64 + dl] = AA;
        red4[(jg * 4 + 1) * 64 + dl] = AB;
        red4[(jg * 4 + 2) * 64 + dl] = AC;
        red4[(jg * 4 + 3) * 64 + dl] = AD;
        __syncthreads();

        const int r = t >> 6;
        const int ri = (r == 0) ? i1a : (r == 1) ? i1b : (r == 2) ? i0a : i0b;
        const float inv = redsc[8 + r];
        float* ob = out + (b * S_ + ri) * D_;
        const int hl = t & 63;
        #pragma unroll
        for (int h = 0; h < 4; h++) {
            int d = hl + h * 64;
            float o = red[(0 * 4 + r) * 256 + d]
                    + red[(1 * 4 + r) * 256 + d]
                    + red[(2 * 4 + r) * 256 + d]
                    + red[(3 * 4 + r) * 256 + d];
            ob[d] = o * inv;
        }
    }
}

// ---------------------------------------------------------------------------
extern "C" void kernel_launch(void* const* d_in, const int* in_sizes, int n_in,
                              void* d_out, int out_size) {
    const float* values = (const float*)d_in[0];
    const float* Wq     = (const float*)d_in[1];
    const float* Wv     = (const float*)d_in[2];
    const float* Vw     = (const float*)d_in[3];
    float* out = (float*)d_out;

    cudaFuncSetAttribute(attn_kernel,
                         cudaFuncAttributeMaxDynamicSharedMemorySize, SMEM_BYTES);

    proj_kernel<<<(B_ * S_) / 8, 256>>>(values, Wq, Wv);
    attn_kernel<<<B_ * 128, 256, SMEM_BYTES>>>(values, Vw, out);
}